// round 13
// baseline (speedup 1.0000x reference)
#include <cuda_runtime.h>
#include <stdint.h>
#include <math.h>
#include <algorithm>

#define Bsz 1024
#define Tt  200
#define Dd  512
#define Hh  256
#define KK  12
#define KMI 30
#define G3H 768
#define NSCAN 141

// ---------------- scratch ----------------------------------------------------
__device__ float g_xproj[(size_t)Tt * Bsz * G3H];  // [T][B][3H]
// packed recurrence weights: g_wv4[(kq*3+g)*Hh + j] = w_hh[g*256+j][4kq..4kq+3]
// +1 kq group of padding so the software prefetch can read one group ahead.
__device__ float4 g_wv4[((Hh / 4) + 1) * 3 * Hh];
__device__ float g_hA[Bsz * Hh];
__device__ float g_centers[KK * Hh];
__device__ float g_hprime[KK * Hh];
__device__ int   g_codes[Bsz];
__device__ int   g_order[Bsz];      // row indices sorted by length desc
__device__ int   g_rowidx[Tt * Bsz];  // compacted alive rows (m = b*T + t)
__device__ int   g_nalive;
__device__ int            g_bar_count;
__device__ volatile int   g_bar_gen;

struct IdxList { int v[KK]; };

__global__ void k_init() {
    int idx = blockIdx.x * blockDim.x + threadIdx.x;
    if (idx < Bsz * Hh) g_hA[idx] = 0.0f;
    if (idx == 0) { g_nalive = 0; g_bar_count = 0; g_bar_gen = 0; }
}

// ---------------- alive-row compaction ---------------------------------------
__global__ void k_alive(const int* __restrict__ lengths) {
    int m = blockIdx.x * 256 + threadIdx.x;
    if (m >= Tt * Bsz) return;
    int b = m / Tt, t = m - b * Tt;
    bool alive = (t < lengths[b]);
    unsigned mask = __ballot_sync(0xffffffffu, alive);
    int lane = threadIdx.x & 31;
    int base = 0;
    if (lane == 0) base = atomicAdd(&g_nalive, __popc(mask));
    base = __shfl_sync(0xffffffffu, base, 0);
    if (alive) g_rowidx[base + __popc(mask & ((1u << lane) - 1u))] = m;
}

// ---------------- repack w_hh: [3H][H] -> float4-blocked ---------------------
__global__ void k_trans(const float* __restrict__ w_hh) {
    int idx = blockIdx.x * 256 + threadIdx.x;
    if (idx < G3H * Hh) {
        int n = idx / Hh, k = idx - n * Hh;  // w_hh[n][k]
        int g = n >> 8, j = n & 255;
        int kq = k >> 2, kr = k & 3;
        reinterpret_cast<float*>(g_wv4)[(size_t)(((kq * 3) + g) * Hh + j) * 4 + kr] =
            w_hh[idx];
    }
}

// ---------------- rank-sort rows by length desc (1024 threads) ---------------
__global__ void k_sort(const int* __restrict__ lengths) {
    __shared__ int ls[Bsz];
    int tid = threadIdx.x;
    if (tid < Bsz) ls[tid] = lengths[tid];
    __syncthreads();
    if (tid < Bsz) {
        int li = ls[tid];
        int r = 0;
        for (int b = 0; b < Bsz; b++) {
            int lb = ls[b];
            r += (lb > li) || (lb == li && b < tid);
        }
        g_order[r] = tid;
    }
}

// ---------------- tf32 helpers ------------------------------------------------
__device__ __forceinline__ uint32_t f2tf32(float f) {
    uint32_t r;
    asm("cvt.rna.tf32.f32 %0, %1;" : "=r"(r) : "f"(f));
    return r;
}
__device__ __forceinline__ void split_tf32(float f, uint32_t& hi, uint32_t& lo) {
    hi = f2tf32(f);
    lo = f2tf32(f - __uint_as_float(hi));
}
__device__ __forceinline__ void mma_tf32(float* c, const uint32_t* a,
                                         const uint32_t* b) {
    asm volatile(
        "mma.sync.aligned.m16n8k8.row.col.f32.tf32.tf32.f32 "
        "{%0,%1,%2,%3}, {%4,%5,%6,%7}, {%8,%9}, {%0,%1,%2,%3};"
        : "+f"(c[0]), "+f"(c[1]), "+f"(c[2]), "+f"(c[3])
        : "r"(a[0]), "r"(a[1]), "r"(a[2]), "r"(a[3]), "r"(b[0]), "r"(b[1]));
}

// ---------------- packed f32x2 helpers (Blackwell FFMA2) ---------------------
typedef unsigned long long u64;
__device__ __forceinline__ void fma2(u64& acc, u64 a, u64 b) {
    asm("fma.rn.f32x2 %0, %1, %2, %3;" : "=l"(acc) : "l"(a), "l"(b), "l"(acc));
}
__device__ __forceinline__ void unpack2(u64 v, float& lo, float& hi) {
    asm("mov.b64 {%0, %1}, %2;" : "=f"(lo), "=f"(hi) : "l"(v));
}

// ---------------- x-projection GEMM (compacted rows, 3xTF32, dbuf) -----------
__global__ void __launch_bounds__(256, 3) k_xproj(const float* __restrict__ x,
                                                  const float* __restrict__ w_ih,
                                                  const float* __restrict__ b_ih) {
    const int m0 = blockIdx.y * 128;
    const int n0 = blockIdx.x * 64;
    const int nalive = g_nalive;
    if (m0 >= nalive) return;

    __shared__ float As[2][16][132];   // fp32, split to tf32 in registers
    __shared__ float Bs[2][16][68];

    const int tid = threadIdx.x;
    const int lr = tid >> 2, lc4 = tid & 3;
    const int wid = tid >> 5, lane = tid & 31;
    const int wm = (wid & 3) * 32;
    const int wn = (wid >> 2) * 32;
    const int lq = lane >> 2, lc = lane & 3;

    int rid0 = m0 + lr, rid1 = m0 + lr + 64;
    const int mrow0 = (rid0 < nalive) ? g_rowidx[rid0] : g_rowidx[0];
    const int mrow1 = (rid1 < nalive) ? g_rowidx[rid1] : g_rowidx[0];

    float c[2][4][4];
#pragma unroll
    for (int mf = 0; mf < 2; mf++)
#pragma unroll
        for (int nf = 0; nf < 4; nf++)
#pragma unroll
            for (int q = 0; q < 4; q++) c[mf][nf][q] = 0.0f;

    {
        float4 v0 = *reinterpret_cast<const float4*>(
            &x[(size_t)mrow0 * Dd + lc4 * 4]);
        float4 v1 = *reinterpret_cast<const float4*>(
            &x[(size_t)mrow1 * Dd + lc4 * 4]);
        float4 vb = *reinterpret_cast<const float4*>(
            &w_ih[(size_t)(n0 + lr) * Dd + lc4 * 4]);
        As[0][lc4 * 4 + 0][lr] = v0.x; As[0][lc4 * 4 + 1][lr] = v0.y;
        As[0][lc4 * 4 + 2][lr] = v0.z; As[0][lc4 * 4 + 3][lr] = v0.w;
        As[0][lc4 * 4 + 0][lr + 64] = v1.x; As[0][lc4 * 4 + 1][lr + 64] = v1.y;
        As[0][lc4 * 4 + 2][lr + 64] = v1.z; As[0][lc4 * 4 + 3][lr + 64] = v1.w;
        Bs[0][lc4 * 4 + 0][lr] = vb.x; Bs[0][lc4 * 4 + 1][lr] = vb.y;
        Bs[0][lc4 * 4 + 2][lr] = vb.z; Bs[0][lc4 * 4 + 3][lr] = vb.w;
    }
    __syncthreads();

    int buf = 0;
    for (int k0 = 0; k0 < Dd; k0 += 16) {
        const bool has_next = (k0 + 16 < Dd);
        float4 pa0, pa1, pb;
        if (has_next) {
            pa0 = *reinterpret_cast<const float4*>(
                &x[(size_t)mrow0 * Dd + k0 + 16 + lc4 * 4]);
            pa1 = *reinterpret_cast<const float4*>(
                &x[(size_t)mrow1 * Dd + k0 + 16 + lc4 * 4]);
            pb = *reinterpret_cast<const float4*>(
                &w_ih[(size_t)(n0 + lr) * Dd + k0 + 16 + lc4 * 4]);
        }

#pragma unroll
        for (int ks = 0; ks < 2; ks++) {
            const int kb = ks * 8;
            uint32_t ah[2][4], al[2][4];
#pragma unroll
            for (int mf = 0; mf < 2; mf++) {
                int r = wm + mf * 16 + lq;
                float f0 = As[buf][kb + lc][r];
                float f1 = As[buf][kb + lc][r + 8];
                float f2 = As[buf][kb + lc + 4][r];
                float f3 = As[buf][kb + lc + 4][r + 8];
                split_tf32(f0, ah[mf][0], al[mf][0]);
                split_tf32(f1, ah[mf][1], al[mf][1]);
                split_tf32(f2, ah[mf][2], al[mf][2]);
                split_tf32(f3, ah[mf][3], al[mf][3]);
            }
            uint32_t bh[4][2], bl[4][2];
#pragma unroll
            for (int nf = 0; nf < 4; nf++) {
                int n = wn + nf * 8 + lq;
                float f0 = Bs[buf][kb + lc][n];
                float f1 = Bs[buf][kb + lc + 4][n];
                split_tf32(f0, bh[nf][0], bl[nf][0]);
                split_tf32(f1, bh[nf][1], bl[nf][1]);
            }
#pragma unroll
            for (int mf = 0; mf < 2; mf++)
#pragma unroll
                for (int nf = 0; nf < 4; nf++) {
                    mma_tf32(c[mf][nf], ah[mf], bh[nf]);  // hi*hi
                    mma_tf32(c[mf][nf], ah[mf], bl[nf]);  // hi*lo
                    mma_tf32(c[mf][nf], al[mf], bh[nf]);  // lo*hi
                }
        }

        if (has_next) {
            int nb = buf ^ 1;
            As[nb][lc4 * 4 + 0][lr] = pa0.x; As[nb][lc4 * 4 + 1][lr] = pa0.y;
            As[nb][lc4 * 4 + 2][lr] = pa0.z; As[nb][lc4 * 4 + 3][lr] = pa0.w;
            As[nb][lc4 * 4 + 0][lr + 64] = pa1.x; As[nb][lc4 * 4 + 1][lr + 64] = pa1.y;
            As[nb][lc4 * 4 + 2][lr + 64] = pa1.z; As[nb][lc4 * 4 + 3][lr + 64] = pa1.w;
            Bs[nb][lc4 * 4 + 0][lr] = pb.x; Bs[nb][lc4 * 4 + 1][lr] = pb.y;
            Bs[nb][lc4 * 4 + 2][lr] = pb.z; Bs[nb][lc4 * 4 + 3][lr] = pb.w;
            __syncthreads();
            buf = nb;
        }
    }

#pragma unroll
    for (int mf = 0; mf < 2; mf++)
#pragma unroll
        for (int half = 0; half < 2; half++) {
            int rid = m0 + wm + mf * 16 + lq + half * 8;
            if (rid >= nalive) continue;
            int row = g_rowidx[rid];
            int b = row / Tt;
            int t = row - b * Tt;
            size_t base = ((size_t)t * Bsz + b) * G3H + n0 + wn;
#pragma unroll
            for (int nf = 0; nf < 4; nf++) {
                int col = nf * 8 + lc * 2;
                float2 o;
                o.x = c[mf][nf][half * 2 + 0] + b_ih[n0 + wn + col];
                o.y = c[mf][nf][half * 2 + 1] + b_ih[n0 + wn + col + 1];
                *reinterpret_cast<float2*>(&g_xproj[base + col]) = o;
            }
        }
}

// ---------------- persistent GRU scan (k-paired FFMA2 + prefetch) ------------
template <int R>
__device__ void scan_body(float (*hs)[Hh], int start,
                          const float* __restrict__ b_hh,
                          const int* __restrict__ lengths) {
    const int j = threadIdx.x;

    int rows[R], lens[R];
#pragma unroll
    for (int i = 0; i < R; i++) {
        int p = start + i;
        rows[i] = (p < Bsz) ? g_order[p] : 0;
        lens[i] = (p < Bsz) ? lengths[rows[i]] : 0;
    }
#pragma unroll
    for (int i = 0; i < R; i++) hs[i][j] = 0.0f;
    __syncthreads();

    int maxlen = 0;
#pragma unroll
    for (int i = 0; i < R; i++) maxlen = max(maxlen, lens[i]);

    const float bhr = b_hh[j], bhz = b_hh[Hh + j], bhn = b_hh[2 * Hh + j];
    const ulonglong2* __restrict__ wbase =
        reinterpret_cast<const ulonglong2*>(g_wv4);

    for (int t = 0; t < maxlen; t++) {
        u64 a2r[R], a2z[R], a2n[R];
#pragma unroll
        for (int i = 0; i < R; i++) { a2r[i] = 0ull; a2z[i] = 0ull; a2n[i] = 0ull; }

        float xr[R], xz[R], xn[R];
        if constexpr (R <= 8) {
#pragma unroll
            for (int i = 0; i < R; i++) {
                if (t < lens[i]) {
                    const float* xp =
                        &g_xproj[((size_t)t * Bsz + rows[i]) * G3H + j];
                    xr[i] = xp[0]; xz[i] = xp[Hh]; xn[i] = xp[2 * Hh];
                } else {
                    xr[i] = 0.f; xz[i] = 0.f; xn[i] = 0.f;
                }
            }
        }

        ulonglong2 wr = wbase[(0 * 3 + 0) * Hh + j];
        ulonglong2 wz = wbase[(0 * 3 + 1) * Hh + j];
        ulonglong2 wn = wbase[(0 * 3 + 2) * Hh + j];
#pragma unroll 2
        for (int kq = 0; kq < Hh / 4; kq++) {
            ulonglong2 wrn = wbase[((kq + 1) * 3 + 0) * Hh + j];
            ulonglong2 wzn = wbase[((kq + 1) * 3 + 1) * Hh + j];
            ulonglong2 wnn = wbase[((kq + 1) * 3 + 2) * Hh + j];
#pragma unroll
            for (int i = 0; i < R; i++) {
                ulonglong2 h2 =
                    *reinterpret_cast<const ulonglong2*>(&hs[i][kq * 4]);
                fma2(a2r[i], h2.x, wr.x); fma2(a2r[i], h2.y, wr.y);
                fma2(a2z[i], h2.x, wz.x); fma2(a2z[i], h2.y, wz.y);
                fma2(a2n[i], h2.x, wn.x); fma2(a2n[i], h2.y, wn.y);
            }
            wr = wrn; wz = wzn; wn = wnn;
        }

        float hnew[R];
#pragma unroll
        for (int i = 0; i < R; i++) {
            float hold = hs[i][j];
            if (t < lens[i]) {
                float lo, hi;
                unpack2(a2r[i], lo, hi); float arv = lo + hi;
                unpack2(a2z[i], lo, hi); float azv = lo + hi;
                unpack2(a2n[i], lo, hi); float anv = lo + hi;
                float xrv, xzv, xnv;
                if constexpr (R <= 8) {
                    xrv = xr[i]; xzv = xz[i]; xnv = xn[i];
                } else {
                    const float* xp =
                        &g_xproj[((size_t)t * Bsz + rows[i]) * G3H + j];
                    xrv = xp[0]; xzv = xp[Hh]; xnv = xp[2 * Hh];
                }
                float r = 1.0f / (1.0f + expf(-(xrv + arv + bhr)));
                float z = 1.0f / (1.0f + expf(-(xzv + azv + bhz)));
                float n = tanhf(xnv + r * (anv + bhn));
                hnew[i] = (1.0f - z) * n + z * hold;
            } else {
                hnew[i] = hold;
            }
        }
        __syncthreads();
#pragma unroll
        for (int i = 0; i < R; i++) hs[i][j] = hnew[i];
        __syncthreads();
    }

#pragma unroll
    for (int i = 0; i < R; i++)
        if (start + i < Bsz)
            g_hA[(size_t)rows[i] * Hh + j] = hs[i][j];
}

__global__ void __launch_bounds__(256, 1) k_scan(const float* __restrict__ b_hh,
                                                 const int* __restrict__ lengths) {
    __shared__ float hs[16][Hh];
    int bb = blockIdx.x;
    if (bb < 48)        scan_body<4>(hs, 4 * bb, b_hh, lengths);
    else if (bb < 80)   scan_body<6>(hs, 192 + 6 * (bb - 48), b_hh, lengths);
    else if (bb < 108)  scan_body<8>(hs, 384 + 8 * (bb - 80), b_hh, lengths);
    else if (bb < 128)  scan_body<11>(hs, 608 + 11 * (bb - 108), b_hh, lengths);
    else                scan_body<16>(hs, 828 + 16 * (bb - 128), b_hh, lengths);
}

// ---------------- fused persistent k-means (12 blocks, spin barrier) ---------
__device__ __forceinline__ void grid_barrier12() {
    __syncthreads();
    if (threadIdx.x == 0) {
        __threadfence();
        int gen = g_bar_gen;
        if (atomicAdd(&g_bar_count, 1) == KK - 1) {
            g_bar_count = 0;
            __threadfence();
            g_bar_gen = gen + 1;
        } else {
            while (g_bar_gen == gen) { }
            __threadfence();
        }
    }
    __syncthreads();
}

__global__ void __launch_bounds__(256, 1) k_kmeans(IdxList il) {
    const int k = blockIdx.x;   // 0..11
    const int tid = threadIdx.x;
    const int warp = tid >> 5, lane = tid & 31;
    __shared__ float cs[KK * Hh];
    __shared__ int list[Bsz];
    __shared__ int cnt_s;

    // init centers (block 0), identical to k_cinit
    if (k == 0) {
#pragma unroll
        for (int c = 0; c < KK; c++)
            g_centers[c * Hh + tid] = g_hA[(size_t)il.v[c] * Hh + tid];
    }
    grid_barrier12();

    for (int it = 0; it < KMI; it++) {
        for (int i = tid; i < KK * Hh; i += 256) cs[i] = g_centers[i];
        __syncthreads();

        // assign: 96 global warps stripe the 1024 rows (same math as k_assign)
        int gw = k * 8 + warp;
        for (int b = gw; b < Bsz; b += 96) {
            float dist[KK];
#pragma unroll
            for (int c = 0; c < KK; c++) dist[c] = 0.0f;
#pragma unroll
            for (int i = 0; i < 8; i++) {
                int d = lane + i * 32;
                float v = g_hA[(size_t)b * Hh + d];
#pragma unroll
                for (int c = 0; c < KK; c++) {
                    float df = v - cs[c * Hh + d];
                    dist[c] += df * df;
                }
            }
#pragma unroll
            for (int c = 0; c < KK; c++)
#pragma unroll
                for (int o = 16; o > 0; o >>= 1)
                    dist[c] += __shfl_xor_sync(0xffffffffu, dist[c], o);
            int code = 0;
            float best = dist[0];
#pragma unroll
            for (int c = 1; c < KK; c++)
                if (dist[c] < best) { best = dist[c]; code = c; }
            if (lane == 0) g_codes[b] = code;
        }
        grid_barrier12();

        // update: block k sums its members in ascending-b order
        if (tid < 32) {
            int cnt = 0;
            for (int base = 0; base < Bsz; base += 32) {
                int code = g_codes[base + tid];
                unsigned m = __ballot_sync(0xffffffffu, code == k);
                int pos = cnt + __popc(m & ((1u << tid) - 1u));
                if (code == k) list[pos] = base + tid;
                cnt += __popc(m);
            }
            if (tid == 0) cnt_s = cnt;
        }
        __syncthreads();
        const int cnt = cnt_s;
        float s = 0.0f;
#pragma unroll 4
        for (int i = 0; i < cnt; i++)
            s += g_hA[(size_t)list[i] * Hh + tid];
        float cold = g_centers[k * Hh + tid];
        g_centers[k * Hh + tid] = (cnt > 0) ? (s / (float)cnt) : cold;
        grid_barrier12();
    }
}

// ---------------- GCN (adj = I -> per-center MLP) ----------------------------
__global__ void k_hprime(const float* __restrict__ g1w, const float* __restrict__ g1b,
                         const float* __restrict__ g2w, const float* __restrict__ g2b) {
    int k = blockIdx.x, j = threadIdx.x;
    __shared__ float c[Hh], tmp[Hh];
    c[j] = g_centers[k * Hh + j];
    __syncthreads();
    float s = g1b[j];
    for (int d = 0; d < Hh; d++) s += c[d] * g1w[(size_t)d * Hh + j];
    tmp[j] = fmaxf(s, 0.0f);
    __syncthreads();
    float s2 = g2b[j];
    for (int d = 0; d < Hh; d++) s2 += tmp[d] * g2w[(size_t)d * Hh + j];
    g_hprime[k * Hh + j] = fmaxf(s2, 0.0f);
}

// ---------------- epilogue ---------------------------------------------------
__global__ void k_epi(const float* __restrict__ wt1w, const float* __restrict__ wt1b,
                      const float* __restrict__ wt2w, const float* __restrict__ wt2b,
                      float* __restrict__ out) {
    __shared__ float cs[KK * Hh], hp[KK * Hh], w1s[Hh], w2s[Hh];
    int tid = threadIdx.x;  // 128
    for (int i = tid; i < KK * Hh; i += 128) { cs[i] = g_centers[i]; hp[i] = g_hprime[i]; }
    for (int i = tid; i < Hh; i += 128)      { w1s[i] = wt1w[i]; w2s[i] = wt2w[i]; }
    __syncthreads();

    int warp = tid >> 5, lane = tid & 31;
    int b = blockIdx.x * 4 + warp;

    float e[KK];
#pragma unroll
    for (int k = 0; k < KK; k++) e[k] = 0.0f;
    float hv[8];
#pragma unroll
    for (int i = 0; i < 8; i++) {
        int d = lane + i * 32;
        float v = g_hA[(size_t)b * Hh + d];
        hv[i] = v;
#pragma unroll
        for (int k = 0; k < KK; k++) e[k] += v * cs[k * Hh + d];
    }
#pragma unroll
    for (int k = 0; k < KK; k++)
#pragma unroll
        for (int o = 16; o > 0; o >>= 1)
            e[k] += __shfl_xor_sync(0xffffffffu, e[k], o);

    float mx = 0.0f;
#pragma unroll
    for (int k = 0; k < KK; k++) { e[k] = fmaxf(e[k], 0.0f); mx = fmaxf(mx, e[k]); }
    float den = 0.0f, sc[KK];
#pragma unroll
    for (int k = 0; k < KK; k++) { sc[k] = expf(e[k] - mx); den += sc[k]; }
    float inv = 1.0f / den;
#pragma unroll
    for (int k = 0; k < KK; k++) sc[k] *= inv;

    float w1p = 0.0f, w2p = 0.0f, cl[8];
#pragma unroll
    for (int i = 0; i < 8; i++) {
        int d = lane + i * 32;
        float s = 0.0f;
#pragma unroll
        for (int k = 0; k < KK; k++) s += sc[k] * hp[k * Hh + d];
        cl[i] = s;
        w1p += s * w1s[d];
        w2p += hv[i] * w2s[d];
    }
#pragma unroll
    for (int o = 16; o > 0; o >>= 1) {
        w1p += __shfl_xor_sync(0xffffffffu, w1p, o);
        w2p += __shfl_xor_sync(0xffffffffu, w2p, o);
    }
    float w1 = 1.0f / (1.0f + expf(-(w1p + wt1b[0])));
    float w2 = 1.0f / (1.0f + expf(-(w2p + wt2b[0])));
    float w1n = w1 / (w1 + w2 + 1e-8f);
#pragma unroll
    for (int i = 0; i < 8; i++) {
        int d = lane + i * 32;
        out[(size_t)b * Hh + d] = w1n * cl[i] + (1.0f - w1n) * hv[i];
    }
}

// ---------------- host: JAX threefry replication -----------------------------
static inline uint32_t rotl32(uint32_t v, int d) { return (v << d) | (v >> (32 - d)); }

static void threefry2x32(uint32_t k0, uint32_t k1, uint32_t c0, uint32_t c1,
                         uint32_t* o0, uint32_t* o1) {
    uint32_t ks0 = k0, ks1 = k1, ks2 = k0 ^ k1 ^ 0x1BD11BDAu;
    uint32_t x0 = c0 + ks0, x1 = c1 + ks1;
    const int rA[4] = {13, 15, 26, 6};
    const int rB[4] = {17, 29, 16, 24};
#define TF4(R) for (int i_ = 0; i_ < 4; i_++) { x0 += x1; x1 = rotl32(x1, R[i_]); x1 ^= x0; }
    TF4(rA); x0 += ks1; x1 += ks2 + 1u;
    TF4(rB); x0 += ks2; x1 += ks0 + 2u;
    TF4(rA); x0 += ks0; x1 += ks1 + 3u;
    TF4(rB); x0 += ks1; x1 += ks2 + 4u;
    TF4(rA); x0 += ks2; x1 += ks0 + 5u;
#undef TF4
    *o0 = x0; *o1 = x1;
}

static void compute_init_indices(int* out12) {
    uint32_t sk0, sk1;
    threefry2x32(0u, 42u, 0u, 1u, &sk0, &sk1);
    uint32_t keys[Bsz];
    for (int i = 0; i < Bsz; i++) {
        uint32_t o0, o1;
        threefry2x32(sk0, sk1, 0u, (uint32_t)i, &o0, &o1);
        keys[i] = o0 ^ o1;
    }
    int idx[Bsz];
    for (int i = 0; i < Bsz; i++) idx[i] = i;
    std::stable_sort(idx, idx + Bsz,
                     [&](int a, int b) { return keys[a] < keys[b]; });
    for (int k = 0; k < KK; k++) out12[k] = idx[k];
}

// ---------------- launch -----------------------------------------------------
extern "C" void kernel_launch(void* const* d_in, const int* in_sizes, int n_in,
                              void* d_out, int out_size) {
    const float* x       = (const float*)d_in[0];
    const int*   lengths = (const int*)  d_in[1];
    const float* w_ih    = (const float*)d_in[2];
    const float* w_hh    = (const float*)d_in[3];
    const float* b_ih    = (const float*)d_in[4];
    const float* b_hh    = (const float*)d_in[5];
    const float* g1w     = (const float*)d_in[6];
    const float* g1b     = (const float*)d_in[7];
    const float* g2w     = (const float*)d_in[8];
    const float* g2b     = (const float*)d_in[9];
    const float* wt1w    = (const float*)d_in[10];
    const float* wt1b    = (const float*)d_in[11];
    const float* wt2w    = (const float*)d_in[12];
    const float* wt2b    = (const float*)d_in[13];
    float* out = (float*)d_out;
    (void)in_sizes; (void)n_in; (void)out_size;

    IdxList il;
    compute_init_indices(il.v);

    k_init<<<1024, 256>>>();
    k_alive<<<(Tt * Bsz + 255) / 256, 256>>>(lengths);
    k_trans<<<(G3H * Hh + 255) / 256, 256>>>(w_hh);
    k_sort<<<1, 1024>>>(lengths);
    k_xproj<<<dim3(12, 1600), 256>>>(x, w_ih, b_ih);
    k_scan<<<NSCAN, 256>>>(b_hh, lengths);
    k_kmeans<<<KK, 256>>>(il);
    k_hprime<<<KK, 256>>>(g1w, g1b, g2w, g2b);
    k_epi<<<256, 128>>>(wt1w, wt1b, wt2w, wt2b, out);
}

// round 14
// speedup vs baseline: 1.0387x; 1.0387x over previous
#include <cuda_runtime.h>
#include <stdint.h>
#include <math.h>
#include <algorithm>

#define Bsz 1024
#define Tt  200
#define Dd  512
#define Hh  256
#define KK  12
#define KMI 30
#define G3H 768
#define NSCAN 141

// ---------------- scratch ----------------------------------------------------
__device__ float g_xproj[(size_t)Tt * Bsz * G3H];  // [T][B][3H]
// packed recurrence weights: g_wv4[(kq*3+g)*Hh + j] = w_hh[g*256+j][4kq..4kq+3]
// +1 kq group of padding so the software prefetch can read one group ahead.
__device__ float4 g_wv4[((Hh / 4) + 1) * 3 * Hh];
__device__ float g_hA[Bsz * Hh];
__device__ float g_centers[KK * Hh];
__device__ float g_hprime[KK * Hh];
__device__ int   g_codes[Bsz];
__device__ int   g_order[Bsz];      // row indices sorted by length desc
__device__ int   g_rowidx[Tt * Bsz];  // compacted alive rows (m = b*T + t)
__device__ int   g_nalive;

struct IdxList { int v[KK]; };

__global__ void k_init() {
    int idx = blockIdx.x * blockDim.x + threadIdx.x;
    if (idx < Bsz * Hh) g_hA[idx] = 0.0f;
    if (idx == 0) g_nalive = 0;
}

// ---------------- alive-row compaction ---------------------------------------
__global__ void k_alive(const int* __restrict__ lengths) {
    int m = blockIdx.x * 256 + threadIdx.x;
    if (m >= Tt * Bsz) return;
    int b = m / Tt, t = m - b * Tt;
    bool alive = (t < lengths[b]);
    unsigned mask = __ballot_sync(0xffffffffu, alive);
    int lane = threadIdx.x & 31;
    int base = 0;
    if (lane == 0) base = atomicAdd(&g_nalive, __popc(mask));
    base = __shfl_sync(0xffffffffu, base, 0);
    if (alive) g_rowidx[base + __popc(mask & ((1u << lane) - 1u))] = m;
}

// ---------------- repack w_hh: [3H][H] -> float4-blocked ---------------------
__global__ void k_trans(const float* __restrict__ w_hh) {
    int idx = blockIdx.x * 256 + threadIdx.x;
    if (idx < G3H * Hh) {
        int n = idx / Hh, k = idx - n * Hh;  // w_hh[n][k]
        int g = n >> 8, j = n & 255;
        int kq = k >> 2, kr = k & 3;
        reinterpret_cast<float*>(g_wv4)[(size_t)(((kq * 3) + g) * Hh + j) * 4 + kr] =
            w_hh[idx];
    }
}

// ---------------- rank-sort rows by length desc (1024 threads) ---------------
__global__ void k_sort(const int* __restrict__ lengths) {
    __shared__ int ls[Bsz];
    int tid = threadIdx.x;
    if (tid < Bsz) ls[tid] = lengths[tid];
    __syncthreads();
    if (tid < Bsz) {
        int li = ls[tid];
        int r = 0;
        for (int b = 0; b < Bsz; b++) {
            int lb = ls[b];
            r += (lb > li) || (lb == li && b < tid);
        }
        g_order[r] = tid;
    }
}

// ---------------- tf32 helpers ------------------------------------------------
__device__ __forceinline__ uint32_t f2tf32(float f) {
    uint32_t r;
    asm("cvt.rna.tf32.f32 %0, %1;" : "=r"(r) : "f"(f));
    return r;
}
__device__ __forceinline__ void split_tf32(float f, uint32_t& hi, uint32_t& lo) {
    hi = f2tf32(f);
    lo = f2tf32(f - __uint_as_float(hi));
}
__device__ __forceinline__ void mma_tf32(float* c, const uint32_t* a,
                                         const uint32_t* b) {
    asm volatile(
        "mma.sync.aligned.m16n8k8.row.col.f32.tf32.tf32.f32 "
        "{%0,%1,%2,%3}, {%4,%5,%6,%7}, {%8,%9}, {%0,%1,%2,%3};"
        : "+f"(c[0]), "+f"(c[1]), "+f"(c[2]), "+f"(c[3])
        : "r"(a[0]), "r"(a[1]), "r"(a[2]), "r"(a[3]), "r"(b[0]), "r"(b[1]));
}

// ---------------- packed f32x2 helpers (Blackwell FFMA2) ---------------------
typedef unsigned long long u64;
__device__ __forceinline__ void fma2(u64& acc, u64 a, u64 b) {
    asm("fma.rn.f32x2 %0, %1, %2, %3;" : "=l"(acc) : "l"(a), "l"(b), "l"(acc));
}
__device__ __forceinline__ void unpack2(u64 v, float& lo, float& hi) {
    asm("mov.b64 {%0, %1}, %2;" : "=f"(lo), "=f"(hi) : "l"(v));
}

// ---------------- x-projection GEMM (compacted rows, 3xTF32, dbuf) -----------
// smem pads chosen so fragment-LDS lc-groups hit disjoint banks:
// A stride 136 (mod 32 = 8), B stride 72 (mod 32 = 8).
__global__ void __launch_bounds__(256, 3) k_xproj(const float* __restrict__ x,
                                                  const float* __restrict__ w_ih,
                                                  const float* __restrict__ b_ih) {
    const int m0 = blockIdx.y * 128;
    const int n0 = blockIdx.x * 64;
    const int nalive = g_nalive;
    if (m0 >= nalive) return;

    __shared__ float As[2][16][136];   // fp32, split to tf32 in registers
    __shared__ float Bs[2][16][72];

    const int tid = threadIdx.x;
    const int lr = tid >> 2, lc4 = tid & 3;
    const int wid = tid >> 5, lane = tid & 31;
    const int wm = (wid & 3) * 32;
    const int wn = (wid >> 2) * 32;
    const int lq = lane >> 2, lc = lane & 3;

    int rid0 = m0 + lr, rid1 = m0 + lr + 64;
    const int mrow0 = (rid0 < nalive) ? g_rowidx[rid0] : g_rowidx[0];
    const int mrow1 = (rid1 < nalive) ? g_rowidx[rid1] : g_rowidx[0];

    float c[2][4][4];
#pragma unroll
    for (int mf = 0; mf < 2; mf++)
#pragma unroll
        for (int nf = 0; nf < 4; nf++)
#pragma unroll
            for (int q = 0; q < 4; q++) c[mf][nf][q] = 0.0f;

    {
        float4 v0 = *reinterpret_cast<const float4*>(
            &x[(size_t)mrow0 * Dd + lc4 * 4]);
        float4 v1 = *reinterpret_cast<const float4*>(
            &x[(size_t)mrow1 * Dd + lc4 * 4]);
        float4 vb = *reinterpret_cast<const float4*>(
            &w_ih[(size_t)(n0 + lr) * Dd + lc4 * 4]);
        As[0][lc4 * 4 + 0][lr] = v0.x; As[0][lc4 * 4 + 1][lr] = v0.y;
        As[0][lc4 * 4 + 2][lr] = v0.z; As[0][lc4 * 4 + 3][lr] = v0.w;
        As[0][lc4 * 4 + 0][lr + 64] = v1.x; As[0][lc4 * 4 + 1][lr + 64] = v1.y;
        As[0][lc4 * 4 + 2][lr + 64] = v1.z; As[0][lc4 * 4 + 3][lr + 64] = v1.w;
        Bs[0][lc4 * 4 + 0][lr] = vb.x; Bs[0][lc4 * 4 + 1][lr] = vb.y;
        Bs[0][lc4 * 4 + 2][lr] = vb.z; Bs[0][lc4 * 4 + 3][lr] = vb.w;
    }
    __syncthreads();

    int buf = 0;
    for (int k0 = 0; k0 < Dd; k0 += 16) {
        const bool has_next = (k0 + 16 < Dd);
        float4 pa0, pa1, pb;
        if (has_next) {
            pa0 = *reinterpret_cast<const float4*>(
                &x[(size_t)mrow0 * Dd + k0 + 16 + lc4 * 4]);
            pa1 = *reinterpret_cast<const float4*>(
                &x[(size_t)mrow1 * Dd + k0 + 16 + lc4 * 4]);
            pb = *reinterpret_cast<const float4*>(
                &w_ih[(size_t)(n0 + lr) * Dd + k0 + 16 + lc4 * 4]);
        }

#pragma unroll
        for (int ks = 0; ks < 2; ks++) {
            const int kb = ks * 8;
            uint32_t ah[2][4], al[2][4];
#pragma unroll
            for (int mf = 0; mf < 2; mf++) {
                int r = wm + mf * 16 + lq;
                float f0 = As[buf][kb + lc][r];
                float f1 = As[buf][kb + lc][r + 8];
                float f2 = As[buf][kb + lc + 4][r];
                float f3 = As[buf][kb + lc + 4][r + 8];
                split_tf32(f0, ah[mf][0], al[mf][0]);
                split_tf32(f1, ah[mf][1], al[mf][1]);
                split_tf32(f2, ah[mf][2], al[mf][2]);
                split_tf32(f3, ah[mf][3], al[mf][3]);
            }
            uint32_t bh[4][2], bl[4][2];
#pragma unroll
            for (int nf = 0; nf < 4; nf++) {
                int n = wn + nf * 8 + lq;
                float f0 = Bs[buf][kb + lc][n];
                float f1 = Bs[buf][kb + lc + 4][n];
                split_tf32(f0, bh[nf][0], bl[nf][0]);
                split_tf32(f1, bh[nf][1], bl[nf][1]);
            }
#pragma unroll
            for (int mf = 0; mf < 2; mf++)
#pragma unroll
                for (int nf = 0; nf < 4; nf++) {
                    mma_tf32(c[mf][nf], ah[mf], bh[nf]);  // hi*hi
                    mma_tf32(c[mf][nf], ah[mf], bl[nf]);  // hi*lo
                    mma_tf32(c[mf][nf], al[mf], bh[nf]);  // lo*hi
                }
        }

        if (has_next) {
            int nb = buf ^ 1;
            As[nb][lc4 * 4 + 0][lr] = pa0.x; As[nb][lc4 * 4 + 1][lr] = pa0.y;
            As[nb][lc4 * 4 + 2][lr] = pa0.z; As[nb][lc4 * 4 + 3][lr] = pa0.w;
            As[nb][lc4 * 4 + 0][lr + 64] = pa1.x; As[nb][lc4 * 4 + 1][lr + 64] = pa1.y;
            As[nb][lc4 * 4 + 2][lr + 64] = pa1.z; As[nb][lc4 * 4 + 3][lr + 64] = pa1.w;
            Bs[nb][lc4 * 4 + 0][lr] = pb.x; Bs[nb][lc4 * 4 + 1][lr] = pb.y;
            Bs[nb][lc4 * 4 + 2][lr] = pb.z; Bs[nb][lc4 * 4 + 3][lr] = pb.w;
            __syncthreads();
            buf = nb;
        }
    }

#pragma unroll
    for (int mf = 0; mf < 2; mf++)
#pragma unroll
        for (int half = 0; half < 2; half++) {
            int rid = m0 + wm + mf * 16 + lq + half * 8;
            if (rid >= nalive) continue;
            int row = g_rowidx[rid];
            int b = row / Tt;
            int t = row - b * Tt;
            size_t base = ((size_t)t * Bsz + b) * G3H + n0 + wn;
#pragma unroll
            for (int nf = 0; nf < 4; nf++) {
                int col = nf * 8 + lc * 2;
                float2 o;
                o.x = c[mf][nf][half * 2 + 0] + b_ih[n0 + wn + col];
                o.y = c[mf][nf][half * 2 + 1] + b_ih[n0 + wn + col + 1];
                *reinterpret_cast<float2*>(&g_xproj[base + col]) = o;
            }
        }
}

// ---------------- persistent GRU scan (k-paired FFMA2 + prefetch) ------------
template <int R>
__device__ void scan_body(float (*hs)[Hh], int start,
                          const float* __restrict__ b_hh,
                          const int* __restrict__ lengths) {
    const int j = threadIdx.x;

    int rows[R], lens[R];
#pragma unroll
    for (int i = 0; i < R; i++) {
        int p = start + i;
        rows[i] = (p < Bsz) ? g_order[p] : 0;
        lens[i] = (p < Bsz) ? lengths[rows[i]] : 0;
    }
#pragma unroll
    for (int i = 0; i < R; i++) hs[i][j] = 0.0f;
    __syncthreads();

    int maxlen = 0;
#pragma unroll
    for (int i = 0; i < R; i++) maxlen = max(maxlen, lens[i]);

    const float bhr = b_hh[j], bhz = b_hh[Hh + j], bhn = b_hh[2 * Hh + j];
    const ulonglong2* __restrict__ wbase =
        reinterpret_cast<const ulonglong2*>(g_wv4);

    for (int t = 0; t < maxlen; t++) {
        u64 a2r[R], a2z[R], a2n[R];
#pragma unroll
        for (int i = 0; i < R; i++) { a2r[i] = 0ull; a2z[i] = 0ull; a2n[i] = 0ull; }

        float xr[R], xz[R], xn[R];
        if constexpr (R <= 8) {
#pragma unroll
            for (int i = 0; i < R; i++) {
                if (t < lens[i]) {
                    const float* xp =
                        &g_xproj[((size_t)t * Bsz + rows[i]) * G3H + j];
                    xr[i] = xp[0]; xz[i] = xp[Hh]; xn[i] = xp[2 * Hh];
                } else {
                    xr[i] = 0.f; xz[i] = 0.f; xn[i] = 0.f;
                }
            }
        }

        ulonglong2 wr = wbase[(0 * 3 + 0) * Hh + j];
        ulonglong2 wz = wbase[(0 * 3 + 1) * Hh + j];
        ulonglong2 wn = wbase[(0 * 3 + 2) * Hh + j];
#pragma unroll 2
        for (int kq = 0; kq < Hh / 4; kq++) {
            ulonglong2 wrn = wbase[((kq + 1) * 3 + 0) * Hh + j];
            ulonglong2 wzn = wbase[((kq + 1) * 3 + 1) * Hh + j];
            ulonglong2 wnn = wbase[((kq + 1) * 3 + 2) * Hh + j];
#pragma unroll
            for (int i = 0; i < R; i++) {
                ulonglong2 h2 =
                    *reinterpret_cast<const ulonglong2*>(&hs[i][kq * 4]);
                fma2(a2r[i], h2.x, wr.x); fma2(a2r[i], h2.y, wr.y);
                fma2(a2z[i], h2.x, wz.x); fma2(a2z[i], h2.y, wz.y);
                fma2(a2n[i], h2.x, wn.x); fma2(a2n[i], h2.y, wn.y);
            }
            wr = wrn; wz = wzn; wn = wnn;
        }

        float hnew[R];
#pragma unroll
        for (int i = 0; i < R; i++) {
            float hold = hs[i][j];
            if (t < lens[i]) {
                float lo, hi;
                unpack2(a2r[i], lo, hi); float arv = lo + hi;
                unpack2(a2z[i], lo, hi); float azv = lo + hi;
                unpack2(a2n[i], lo, hi); float anv = lo + hi;
                float xrv, xzv, xnv;
                if constexpr (R <= 8) {
                    xrv = xr[i]; xzv = xz[i]; xnv = xn[i];
                } else {
                    const float* xp =
                        &g_xproj[((size_t)t * Bsz + rows[i]) * G3H + j];
                    xrv = xp[0]; xzv = xp[Hh]; xnv = xp[2 * Hh];
                }
                float r = 1.0f / (1.0f + expf(-(xrv + arv + bhr)));
                float z = 1.0f / (1.0f + expf(-(xzv + azv + bhz)));
                float n = tanhf(xnv + r * (anv + bhn));
                hnew[i] = (1.0f - z) * n + z * hold;
            } else {
                hnew[i] = hold;
            }
        }
        __syncthreads();
#pragma unroll
        for (int i = 0; i < R; i++) hs[i][j] = hnew[i];
        __syncthreads();
    }

#pragma unroll
    for (int i = 0; i < R; i++)
        if (start + i < Bsz)
            g_hA[(size_t)rows[i] * Hh + j] = hs[i][j];
}

__global__ void __launch_bounds__(256, 1) k_scan(const float* __restrict__ b_hh,
                                                 const int* __restrict__ lengths) {
    __shared__ float hs[16][Hh];
    int bb = blockIdx.x;
    if (bb < 48)        scan_body<4>(hs, 4 * bb, b_hh, lengths);
    else if (bb < 80)   scan_body<6>(hs, 192 + 6 * (bb - 48), b_hh, lengths);
    else if (bb < 108)  scan_body<8>(hs, 384 + 8 * (bb - 80), b_hh, lengths);
    else if (bb < 128)  scan_body<11>(hs, 608 + 11 * (bb - 108), b_hh, lengths);
    else                scan_body<16>(hs, 828 + 16 * (bb - 128), b_hh, lengths);
}

// ---------------- kmeans (R12 proven configuration) ---------------------------
__global__ void k_cinit(IdxList il) {
    int d = threadIdx.x;
#pragma unroll
    for (int k = 0; k < KK; k++)
        g_centers[k * Hh + d] = g_hA[(size_t)il.v[k] * Hh + d];
}

__global__ void k_assign() {
    __shared__ float cs[KK * Hh];
    int tid = threadIdx.x;  // 128
    for (int i = tid; i < KK * Hh; i += 128) cs[i] = g_centers[i];
    __syncthreads();

    int warp = tid >> 5, lane = tid & 31;
    int b = blockIdx.x * 4 + warp;

    float dist[KK];
#pragma unroll
    for (int k = 0; k < KK; k++) dist[k] = 0.0f;
#pragma unroll
    for (int i = 0; i < 8; i++) {
        int d = lane + i * 32;
        float v = g_hA[(size_t)b * Hh + d];
#pragma unroll
        for (int k = 0; k < KK; k++) {
            float df = v - cs[k * Hh + d];
            dist[k] += df * df;
        }
    }
#pragma unroll
    for (int k = 0; k < KK; k++)
#pragma unroll
        for (int o = 16; o > 0; o >>= 1)
            dist[k] += __shfl_xor_sync(0xffffffffu, dist[k], o);

    int code = 0;
    float best = dist[0];
#pragma unroll
    for (int k = 1; k < KK; k++)
        if (dist[k] < best) { best = dist[k]; code = k; }
    if (lane == 0) g_codes[b] = code;
}

__global__ void k_update() {
    __shared__ int list[Bsz];
    __shared__ int cnt_s;
    const int k = blockIdx.x, tid = threadIdx.x;

    if (tid < 32) {
        int cnt = 0;
        for (int base = 0; base < Bsz; base += 32) {
            int code = g_codes[base + tid];
            unsigned m = __ballot_sync(0xffffffffu, code == k);
            int pos = cnt + __popc(m & ((1u << tid) - 1u));
            if (code == k) list[pos] = base + tid;
            cnt += __popc(m);
        }
        if (tid == 0) cnt_s = cnt;
    }
    __syncthreads();

    const int cnt = cnt_s;
    const int d = tid;
    float s = 0.0f;
#pragma unroll 4
    for (int i = 0; i < cnt; i++)
        s += g_hA[(size_t)list[i] * Hh + d];
    float cold = g_centers[k * Hh + d];
    g_centers[k * Hh + d] = (cnt > 0) ? (s / (float)cnt) : cold;
}

// ---------------- GCN (adj = I -> per-center MLP) ----------------------------
__global__ void k_hprime(const float* __restrict__ g1w, const float* __restrict__ g1b,
                         const float* __restrict__ g2w, const float* __restrict__ g2b) {
    int k = blockIdx.x, j = threadIdx.x;
    __shared__ float c[Hh], tmp[Hh];
    c[j] = g_centers[k * Hh + j];
    __syncthreads();
    float s = g1b[j];
    for (int d = 0; d < Hh; d++) s += c[d] * g1w[(size_t)d * Hh + j];
    tmp[j] = fmaxf(s, 0.0f);
    __syncthreads();
    float s2 = g2b[j];
    for (int d = 0; d < Hh; d++) s2 += tmp[d] * g2w[(size_t)d * Hh + j];
    g_hprime[k * Hh + j] = fmaxf(s2, 0.0f);
}

// ---------------- epilogue ---------------------------------------------------
__global__ void k_epi(const float* __restrict__ wt1w, const float* __restrict__ wt1b,
                      const float* __restrict__ wt2w, const float* __restrict__ wt2b,
                      float* __restrict__ out) {
    __shared__ float cs[KK * Hh], hp[KK * Hh], w1s[Hh], w2s[Hh];
    int tid = threadIdx.x;  // 128
    for (int i = tid; i < KK * Hh; i += 128) { cs[i] = g_centers[i]; hp[i] = g_hprime[i]; }
    for (int i = tid; i < Hh; i += 128)      { w1s[i] = wt1w[i]; w2s[i] = wt2w[i]; }
    __syncthreads();

    int warp = tid >> 5, lane = tid & 31;
    int b = blockIdx.x * 4 + warp;

    float e[KK];
#pragma unroll
    for (int k = 0; k < KK; k++) e[k] = 0.0f;
    float hv[8];
#pragma unroll
    for (int i = 0; i < 8; i++) {
        int d = lane + i * 32;
        float v = g_hA[(size_t)b * Hh + d];
        hv[i] = v;
#pragma unroll
        for (int k = 0; k < KK; k++) e[k] += v * cs[k * Hh + d];
    }
#pragma unroll
    for (int k = 0; k < KK; k++)
#pragma unroll
        for (int o = 16; o > 0; o >>= 1)
            e[k] += __shfl_xor_sync(0xffffffffu, e[k], o);

    float mx = 0.0f;
#pragma unroll
    for (int k = 0; k < KK; k++) { e[k] = fmaxf(e[k], 0.0f); mx = fmaxf(mx, e[k]); }
    float den = 0.0f, sc[KK];
#pragma unroll
    for (int k = 0; k < KK; k++) { sc[k] = expf(e[k] - mx); den += sc[k]; }
    float inv = 1.0f / den;
#pragma unroll
    for (int k = 0; k < KK; k++) sc[k] *= inv;

    float w1p = 0.0f, w2p = 0.0f, cl[8];
#pragma unroll
    for (int i = 0; i < 8; i++) {
        int d = lane + i * 32;
        float s = 0.0f;
#pragma unroll
        for (int k = 0; k < KK; k++) s += sc[k] * hp[k * Hh + d];
        cl[i] = s;
        w1p += s * w1s[d];
        w2p += hv[i] * w2s[d];
    }
#pragma unroll
    for (int o = 16; o > 0; o >>= 1) {
        w1p += __shfl_xor_sync(0xffffffffu, w1p, o);
        w2p += __shfl_xor_sync(0xffffffffu, w2p, o);
    }
    float w1 = 1.0f / (1.0f + expf(-(w1p + wt1b[0])));
    float w2 = 1.0f / (1.0f + expf(-(w2p + wt2b[0])));
    float w1n = w1 / (w1 + w2 + 1e-8f);
#pragma unroll
    for (int i = 0; i < 8; i++) {
        int d = lane + i * 32;
        out[(size_t)b * Hh + d] = w1n * cl[i] + (1.0f - w1n) * hv[i];
    }
}

// ---------------- host: JAX threefry replication -----------------------------
static inline uint32_t rotl32(uint32_t v, int d) { return (v << d) | (v >> (32 - d)); }

static void threefry2x32(uint32_t k0, uint32_t k1, uint32_t c0, uint32_t c1,
                         uint32_t* o0, uint32_t* o1) {
    uint32_t ks0 = k0, ks1 = k1, ks2 = k0 ^ k1 ^ 0x1BD11BDAu;
    uint32_t x0 = c0 + ks0, x1 = c1 + ks1;
    const int rA[4] = {13, 15, 26, 6};
    const int rB[4] = {17, 29, 16, 24};
#define TF4(R) for (int i_ = 0; i_ < 4; i_++) { x0 += x1; x1 = rotl32(x1, R[i_]); x1 ^= x0; }
    TF4(rA); x0 += ks1; x1 += ks2 + 1u;
    TF4(rB); x0 += ks2; x1 += ks0 + 2u;
    TF4(rA); x0 += ks0; x1 += ks1 + 3u;
    TF4(rB); x0 += ks1; x1 += ks2 + 4u;
    TF4(rA); x0 += ks2; x1 += ks0 + 5u;
#undef TF4
    *o0 = x0; *o1 = x1;
}

static void compute_init_indices(int* out12) {
    uint32_t sk0, sk1;
    threefry2x32(0u, 42u, 0u, 1u, &sk0, &sk1);
    uint32_t keys[Bsz];
    for (int i = 0; i < Bsz; i++) {
        uint32_t o0, o1;
        threefry2x32(sk0, sk1, 0u, (uint32_t)i, &o0, &o1);
        keys[i] = o0 ^ o1;
    }
    int idx[Bsz];
    for (int i = 0; i < Bsz; i++) idx[i] = i;
    std::stable_sort(idx, idx + Bsz,
                     [&](int a, int b) { return keys[a] < keys[b]; });
    for (int k = 0; k < KK; k++) out12[k] = idx[k];
}

// ---------------- launch -----------------------------------------------------
extern "C" void kernel_launch(void* const* d_in, const int* in_sizes, int n_in,
                              void* d_out, int out_size) {
    const float* x       = (const float*)d_in[0];
    const int*   lengths = (const int*)  d_in[1];
    const float* w_ih    = (const float*)d_in[2];
    const float* w_hh    = (const float*)d_in[3];
    const float* b_ih    = (const float*)d_in[4];
    const float* b_hh    = (const float*)d_in[5];
    const float* g1w     = (const float*)d_in[6];
    const float* g1b     = (const float*)d_in[7];
    const float* g2w     = (const float*)d_in[8];
    const float* g2b     = (const float*)d_in[9];
    const float* wt1w    = (const float*)d_in[10];
    const float* wt1b    = (const float*)d_in[11];
    const float* wt2w    = (const float*)d_in[12];
    const float* wt2b    = (const float*)d_in[13];
    float* out = (float*)d_out;
    (void)in_sizes; (void)n_in; (void)out_size;

    IdxList il;
    compute_init_indices(il.v);

    k_init<<<1024, 256>>>();
    k_alive<<<(Tt * Bsz + 255) / 256, 256>>>(lengths);
    k_trans<<<(G3H * Hh + 255) / 256, 256>>>(w_hh);
    k_sort<<<1, 1024>>>(lengths);
    k_xproj<<<dim3(12, 1600), 256>>>(x, w_ih, b_ih);
    k_scan<<<NSCAN, 256>>>(b_hh, lengths);
    k_cinit<<<1, 256>>>(il);
    for (int it = 0; it < KMI; it++) {
        k_assign<<<256, 128>>>();
        k_update<<<KK, 256>>>();
    }
    k_hprime<<<KK, 256>>>(g1w, g1b, g2w, g2b);
    k_epi<<<256, 128>>>(wt1w, wt1b, wt2w, wt2b, out);
}

// round 15
// speedup vs baseline: 1.1680x; 1.1244x over previous
#include <cuda_runtime.h>
#include <stdint.h>
#include <math.h>
#include <algorithm>

#define Bsz 1024
#define Tt  200
#define Dd  512
#define Hh  256
#define KK  12
#define KMI 30
#define G3H 768
#define NSCAN 141

// ---------------- scratch ----------------------------------------------------
__device__ float g_xproj[(size_t)Tt * Bsz * G3H];  // [T][B][3H]
// packed recurrence weights: g_wv4[(kq*3+g)*Hh + j] = w_hh[g*256+j][4kq..4kq+3]
// +5 kq groups of padding so deep software prefetch reads stay in-bounds.
__device__ float4 g_wv4[((Hh / 4) + 5) * 3 * Hh];
__device__ float g_hA[Bsz * Hh];
__device__ float g_centers[KK * Hh];
__device__ float g_hprime[KK * Hh];
__device__ int   g_codes[Bsz];
__device__ int   g_order[Bsz];      // row indices sorted by length desc
__device__ int   g_rowidx[Tt * Bsz];  // compacted alive rows (m = b*T + t)
__device__ int   g_nalive;

struct IdxList { int v[KK]; };

__global__ void k_init() {
    int idx = blockIdx.x * blockDim.x + threadIdx.x;
    if (idx < Bsz * Hh) g_hA[idx] = 0.0f;
    if (idx == 0) g_nalive = 0;
}

// ---------------- alive-row compaction ---------------------------------------
__global__ void k_alive(const int* __restrict__ lengths) {
    int m = blockIdx.x * 256 + threadIdx.x;
    if (m >= Tt * Bsz) return;
    int b = m / Tt, t = m - b * Tt;
    bool alive = (t < lengths[b]);
    unsigned mask = __ballot_sync(0xffffffffu, alive);
    int lane = threadIdx.x & 31;
    int base = 0;
    if (lane == 0) base = atomicAdd(&g_nalive, __popc(mask));
    base = __shfl_sync(0xffffffffu, base, 0);
    if (alive) g_rowidx[base + __popc(mask & ((1u << lane) - 1u))] = m;
}

// ---------------- repack w_hh: [3H][H] -> float4-blocked ---------------------
__global__ void k_trans(const float* __restrict__ w_hh) {
    int idx = blockIdx.x * 256 + threadIdx.x;
    if (idx < G3H * Hh) {
        int n = idx / Hh, k = idx - n * Hh;  // w_hh[n][k]
        int g = n >> 8, j = n & 255;
        int kq = k >> 2, kr = k & 3;
        reinterpret_cast<float*>(g_wv4)[(size_t)(((kq * 3) + g) * Hh + j) * 4 + kr] =
            w_hh[idx];
    }
}

// ---------------- rank-sort rows by length desc (1024 threads) ---------------
__global__ void k_sort(const int* __restrict__ lengths) {
    __shared__ int ls[Bsz];
    int tid = threadIdx.x;
    if (tid < Bsz) ls[tid] = lengths[tid];
    __syncthreads();
    if (tid < Bsz) {
        int li = ls[tid];
        int r = 0;
        for (int b = 0; b < Bsz; b++) {
            int lb = ls[b];
            r += (lb > li) || (lb == li && b < tid);
        }
        g_order[r] = tid;
    }
}

// ---------------- tf32 helpers ------------------------------------------------
__device__ __forceinline__ uint32_t f2tf32(float f) {
    uint32_t r;
    asm("cvt.rna.tf32.f32 %0, %1;" : "=r"(r) : "f"(f));
    return r;
}
__device__ __forceinline__ void split_tf32(float f, uint32_t& hi, uint32_t& lo) {
    hi = f2tf32(f);
    lo = f2tf32(f - __uint_as_float(hi));
}
__device__ __forceinline__ void mma_tf32(float* c, const uint32_t* a,
                                         const uint32_t* b) {
    asm volatile(
        "mma.sync.aligned.m16n8k8.row.col.f32.tf32.tf32.f32 "
        "{%0,%1,%2,%3}, {%4,%5,%6,%7}, {%8,%9}, {%0,%1,%2,%3};"
        : "+f"(c[0]), "+f"(c[1]), "+f"(c[2]), "+f"(c[3])
        : "r"(a[0]), "r"(a[1]), "r"(a[2]), "r"(a[3]), "r"(b[0]), "r"(b[1]));
}

// ---------------- packed f32x2 helpers (Blackwell FFMA2) ---------------------
typedef unsigned long long u64;
__device__ __forceinline__ void fma2(u64& acc, u64 a, u64 b) {
    asm("fma.rn.f32x2 %0, %1, %2, %3;" : "=l"(acc) : "l"(a), "l"(b), "l"(acc));
}
__device__ __forceinline__ void unpack2(u64 v, float& lo, float& hi) {
    asm("mov.b64 {%0, %1}, %2;" : "=f"(lo), "=f"(hi) : "l"(v));
}

// ---------------- x-projection GEMM (compacted rows, 3xTF32, dbuf) -----------
__global__ void __launch_bounds__(256, 3) k_xproj(const float* __restrict__ x,
                                                  const float* __restrict__ w_ih,
                                                  const float* __restrict__ b_ih) {
    const int m0 = blockIdx.y * 128;
    const int n0 = blockIdx.x * 64;
    const int nalive = g_nalive;
    if (m0 >= nalive) return;

    __shared__ float As[2][16][136];
    __shared__ float Bs[2][16][72];

    const int tid = threadIdx.x;
    const int lr = tid >> 2, lc4 = tid & 3;
    const int wid = tid >> 5, lane = tid & 31;
    const int wm = (wid & 3) * 32;
    const int wn = (wid >> 2) * 32;
    const int lq = lane >> 2, lc = lane & 3;

    int rid0 = m0 + lr, rid1 = m0 + lr + 64;
    const int mrow0 = (rid0 < nalive) ? g_rowidx[rid0] : g_rowidx[0];
    const int mrow1 = (rid1 < nalive) ? g_rowidx[rid1] : g_rowidx[0];

    float c[2][4][4];
#pragma unroll
    for (int mf = 0; mf < 2; mf++)
#pragma unroll
        for (int nf = 0; nf < 4; nf++)
#pragma unroll
            for (int q = 0; q < 4; q++) c[mf][nf][q] = 0.0f;

    {
        float4 v0 = *reinterpret_cast<const float4*>(
            &x[(size_t)mrow0 * Dd + lc4 * 4]);
        float4 v1 = *reinterpret_cast<const float4*>(
            &x[(size_t)mrow1 * Dd + lc4 * 4]);
        float4 vb = *reinterpret_cast<const float4*>(
            &w_ih[(size_t)(n0 + lr) * Dd + lc4 * 4]);
        As[0][lc4 * 4 + 0][lr] = v0.x; As[0][lc4 * 4 + 1][lr] = v0.y;
        As[0][lc4 * 4 + 2][lr] = v0.z; As[0][lc4 * 4 + 3][lr] = v0.w;
        As[0][lc4 * 4 + 0][lr + 64] = v1.x; As[0][lc4 * 4 + 1][lr + 64] = v1.y;
        As[0][lc4 * 4 + 2][lr + 64] = v1.z; As[0][lc4 * 4 + 3][lr + 64] = v1.w;
        Bs[0][lc4 * 4 + 0][lr] = vb.x; Bs[0][lc4 * 4 + 1][lr] = vb.y;
        Bs[0][lc4 * 4 + 2][lr] = vb.z; Bs[0][lc4 * 4 + 3][lr] = vb.w;
    }
    __syncthreads();

    int buf = 0;
    for (int k0 = 0; k0 < Dd; k0 += 16) {
        const bool has_next = (k0 + 16 < Dd);
        float4 pa0, pa1, pb;
        if (has_next) {
            pa0 = *reinterpret_cast<const float4*>(
                &x[(size_t)mrow0 * Dd + k0 + 16 + lc4 * 4]);
            pa1 = *reinterpret_cast<const float4*>(
                &x[(size_t)mrow1 * Dd + k0 + 16 + lc4 * 4]);
            pb = *reinterpret_cast<const float4*>(
                &w_ih[(size_t)(n0 + lr) * Dd + k0 + 16 + lc4 * 4]);
        }

#pragma unroll
        for (int ks = 0; ks < 2; ks++) {
            const int kb = ks * 8;
            uint32_t ah[2][4], al[2][4];
#pragma unroll
            for (int mf = 0; mf < 2; mf++) {
                int r = wm + mf * 16 + lq;
                float f0 = As[buf][kb + lc][r];
                float f1 = As[buf][kb + lc][r + 8];
                float f2 = As[buf][kb + lc + 4][r];
                float f3 = As[buf][kb + lc + 4][r + 8];
                split_tf32(f0, ah[mf][0], al[mf][0]);
                split_tf32(f1, ah[mf][1], al[mf][1]);
                split_tf32(f2, ah[mf][2], al[mf][2]);
                split_tf32(f3, ah[mf][3], al[mf][3]);
            }
            uint32_t bh[4][2], bl[4][2];
#pragma unroll
            for (int nf = 0; nf < 4; nf++) {
                int n = wn + nf * 8 + lq;
                float f0 = Bs[buf][kb + lc][n];
                float f1 = Bs[buf][kb + lc + 4][n];
                split_tf32(f0, bh[nf][0], bl[nf][0]);
                split_tf32(f1, bh[nf][1], bl[nf][1]);
            }
#pragma unroll
            for (int mf = 0; mf < 2; mf++)
#pragma unroll
                for (int nf = 0; nf < 4; nf++) {
                    mma_tf32(c[mf][nf], ah[mf], bh[nf]);  // hi*hi
                    mma_tf32(c[mf][nf], ah[mf], bl[nf]);  // hi*lo
                    mma_tf32(c[mf][nf], al[mf], bh[nf]);  // lo*hi
                }
        }

        if (has_next) {
            int nb = buf ^ 1;
            As[nb][lc4 * 4 + 0][lr] = pa0.x; As[nb][lc4 * 4 + 1][lr] = pa0.y;
            As[nb][lc4 * 4 + 2][lr] = pa0.z; As[nb][lc4 * 4 + 3][lr] = pa0.w;
            As[nb][lc4 * 4 + 0][lr + 64] = pa1.x; As[nb][lc4 * 4 + 1][lr + 64] = pa1.y;
            As[nb][lc4 * 4 + 2][lr + 64] = pa1.z; As[nb][lc4 * 4 + 3][lr + 64] = pa1.w;
            Bs[nb][lc4 * 4 + 0][lr] = pb.x; Bs[nb][lc4 * 4 + 1][lr] = pb.y;
            Bs[nb][lc4 * 4 + 2][lr] = pb.z; Bs[nb][lc4 * 4 + 3][lr] = pb.w;
            __syncthreads();
            buf = nb;
        }
    }

#pragma unroll
    for (int mf = 0; mf < 2; mf++)
#pragma unroll
        for (int half = 0; half < 2; half++) {
            int rid = m0 + wm + mf * 16 + lq + half * 8;
            if (rid >= nalive) continue;
            int row = g_rowidx[rid];
            int b = row / Tt;
            int t = row - b * Tt;
            size_t base = ((size_t)t * Bsz + b) * G3H + n0 + wn;
#pragma unroll
            for (int nf = 0; nf < 4; nf++) {
                int col = nf * 8 + lc * 2;
                float2 o;
                o.x = c[mf][nf][half * 2 + 0] + b_ih[n0 + wn + col];
                o.y = c[mf][nf][half * 2 + 1] + b_ih[n0 + wn + col + 1];
                *reinterpret_cast<float2*>(&g_xproj[base + col]) = o;
            }
        }
}

// ---------------- persistent GRU scan (FFMA2, depth-PD weight prefetch) ------
// PD register-resident weight groups cover L2 latency (~240 cyc): each slot is
// consumed, then immediately refilled for kq+PD. Accumulation order unchanged.
template <int R, int PD>
__device__ void scan_body(float (*hs)[Hh], int start,
                          const float* __restrict__ b_hh,
                          const int* __restrict__ lengths) {
    const int j = threadIdx.x;

    int rows[R], lens[R];
#pragma unroll
    for (int i = 0; i < R; i++) {
        int p = start + i;
        rows[i] = (p < Bsz) ? g_order[p] : 0;
        lens[i] = (p < Bsz) ? lengths[rows[i]] : 0;
    }
#pragma unroll
    for (int i = 0; i < R; i++) hs[i][j] = 0.0f;
    __syncthreads();

    int maxlen = 0;
#pragma unroll
    for (int i = 0; i < R; i++) maxlen = max(maxlen, lens[i]);

    const float bhr = b_hh[j], bhz = b_hh[Hh + j], bhn = b_hh[2 * Hh + j];
    const ulonglong2* __restrict__ wbase =
        reinterpret_cast<const ulonglong2*>(g_wv4);

    for (int t = 0; t < maxlen; t++) {
        u64 a2r[R], a2z[R], a2n[R];
#pragma unroll
        for (int i = 0; i < R; i++) { a2r[i] = 0ull; a2z[i] = 0ull; a2n[i] = 0ull; }

        float xr[R], xz[R], xn[R];
        if constexpr (R <= 8) {
#pragma unroll
            for (int i = 0; i < R; i++) {
                if (t < lens[i]) {
                    const float* xp =
                        &g_xproj[((size_t)t * Bsz + rows[i]) * G3H + j];
                    xr[i] = xp[0]; xz[i] = xp[Hh]; xn[i] = xp[2 * Hh];
                } else {
                    xr[i] = 0.f; xz[i] = 0.f; xn[i] = 0.f;
                }
            }
        }

        ulonglong2 wr[PD], wz[PD], wn[PD];
#pragma unroll
        for (int u = 0; u < PD; u++) {
            wr[u] = wbase[(u * 3 + 0) * Hh + j];
            wz[u] = wbase[(u * 3 + 1) * Hh + j];
            wn[u] = wbase[(u * 3 + 2) * Hh + j];
        }

        for (int kq = 0; kq < Hh / 4; kq += PD) {
#pragma unroll
            for (int u = 0; u < PD; u++) {
                ulonglong2 cwr = wr[u], cwz = wz[u], cwn = wn[u];
                // refill slot for kq+u+PD (padded array keeps reads in-bounds)
                wr[u] = wbase[((kq + u + PD) * 3 + 0) * Hh + j];
                wz[u] = wbase[((kq + u + PD) * 3 + 1) * Hh + j];
                wn[u] = wbase[((kq + u + PD) * 3 + 2) * Hh + j];
#pragma unroll
                for (int i = 0; i < R; i++) {
                    ulonglong2 h2 =
                        *reinterpret_cast<const ulonglong2*>(&hs[i][(kq + u) * 4]);
                    fma2(a2r[i], h2.x, cwr.x); fma2(a2r[i], h2.y, cwr.y);
                    fma2(a2z[i], h2.x, cwz.x); fma2(a2z[i], h2.y, cwz.y);
                    fma2(a2n[i], h2.x, cwn.x); fma2(a2n[i], h2.y, cwn.y);
                }
            }
        }

        float hnew[R];
#pragma unroll
        for (int i = 0; i < R; i++) {
            float hold = hs[i][j];
            if (t < lens[i]) {
                float lo, hi;
                unpack2(a2r[i], lo, hi); float arv = lo + hi;
                unpack2(a2z[i], lo, hi); float azv = lo + hi;
                unpack2(a2n[i], lo, hi); float anv = lo + hi;
                float xrv, xzv, xnv;
                if constexpr (R <= 8) {
                    xrv = xr[i]; xzv = xz[i]; xnv = xn[i];
                } else {
                    const float* xp =
                        &g_xproj[((size_t)t * Bsz + rows[i]) * G3H + j];
                    xrv = xp[0]; xzv = xp[Hh]; xnv = xp[2 * Hh];
                }
                float r = 1.0f / (1.0f + expf(-(xrv + arv + bhr)));
                float z = 1.0f / (1.0f + expf(-(xzv + azv + bhz)));
                float n = tanhf(xnv + r * (anv + bhn));
                hnew[i] = (1.0f - z) * n + z * hold;
            } else {
                hnew[i] = hold;
            }
        }
        __syncthreads();
#pragma unroll
        for (int i = 0; i < R; i++) hs[i][j] = hnew[i];
        __syncthreads();
    }

#pragma unroll
    for (int i = 0; i < R; i++)
        if (start + i < Bsz)
            g_hA[(size_t)rows[i] * Hh + j] = hs[i][j];
}

__global__ void __launch_bounds__(256, 1) k_scan(const float* __restrict__ b_hh,
                                                 const int* __restrict__ lengths) {
    __shared__ float hs[16][Hh];
    int bb = blockIdx.x;
    if (bb < 48)        scan_body<4, 4>(hs, 4 * bb, b_hh, lengths);
    else if (bb < 80)   scan_body<6, 4>(hs, 192 + 6 * (bb - 48), b_hh, lengths);
    else if (bb < 108)  scan_body<8, 2>(hs, 384 + 8 * (bb - 80), b_hh, lengths);
    else if (bb < 128)  scan_body<11, 2>(hs, 608 + 11 * (bb - 108), b_hh, lengths);
    else                scan_body<16, 2>(hs, 828 + 16 * (bb - 128), b_hh, lengths);
}

// ---------------- kmeans (R12 proven configuration) ---------------------------
__global__ void k_cinit(IdxList il) {
    int d = threadIdx.x;
#pragma unroll
    for (int k = 0; k < KK; k++)
        g_centers[k * Hh + d] = g_hA[(size_t)il.v[k] * Hh + d];
}

__global__ void k_assign() {
    __shared__ float cs[KK * Hh];
    int tid = threadIdx.x;  // 128
    for (int i = tid; i < KK * Hh; i += 128) cs[i] = g_centers[i];
    __syncthreads();

    int warp = tid >> 5, lane = tid & 31;
    int b = blockIdx.x * 4 + warp;

    float dist[KK];
#pragma unroll
    for (int k = 0; k < KK; k++) dist[k] = 0.0f;
#pragma unroll
    for (int i = 0; i < 8; i++) {
        int d = lane + i * 32;
        float v = g_hA[(size_t)b * Hh + d];
#pragma unroll
        for (int k = 0; k < KK; k++) {
            float df = v - cs[k * Hh + d];
            dist[k] += df * df;
        }
    }
#pragma unroll
    for (int k = 0; k < KK; k++)
#pragma unroll
        for (int o = 16; o > 0; o >>= 1)
            dist[k] += __shfl_xor_sync(0xffffffffu, dist[k], o);

    int code = 0;
    float best = dist[0];
#pragma unroll
    for (int k = 1; k < KK; k++)
        if (dist[k] < best) { best = dist[k]; code = k; }
    if (lane == 0) g_codes[b] = code;
}

__global__ void k_update() {
    __shared__ int list[Bsz];
    __shared__ int cnt_s;
    const int k = blockIdx.x, tid = threadIdx.x;

    if (tid < 32) {
        int cnt = 0;
        for (int base = 0; base < Bsz; base += 32) {
            int code = g_codes[base + tid];
            unsigned m = __ballot_sync(0xffffffffu, code == k);
            int pos = cnt + __popc(m & ((1u << tid) - 1u));
            if (code == k) list[pos] = base + tid;
            cnt += __popc(m);
        }
        if (tid == 0) cnt_s = cnt;
    }
    __syncthreads();

    const int cnt = cnt_s;
    const int d = tid;
    float s = 0.0f;
#pragma unroll 4
    for (int i = 0; i < cnt; i++)
        s += g_hA[(size_t)list[i] * Hh + d];
    float cold = g_centers[k * Hh + d];
    g_centers[k * Hh + d] = (cnt > 0) ? (s / (float)cnt) : cold;
}

// ---------------- GCN (adj = I -> per-center MLP) ----------------------------
__global__ void k_hprime(const float* __restrict__ g1w, const float* __restrict__ g1b,
                         const float* __restrict__ g2w, const float* __restrict__ g2b) {
    int k = blockIdx.x, j = threadIdx.x;
    __shared__ float c[Hh], tmp[Hh];
    c[j] = g_centers[k * Hh + j];
    __syncthreads();
    float s = g1b[j];
    for (int d = 0; d < Hh; d++) s += c[d] * g1w[(size_t)d * Hh + j];
    tmp[j] = fmaxf(s, 0.0f);
    __syncthreads();
    float s2 = g2b[j];
    for (int d = 0; d < Hh; d++) s2 += tmp[d] * g2w[(size_t)d * Hh + j];
    g_hprime[k * Hh + j] = fmaxf(s2, 0.0f);
}

// ---------------- epilogue ---------------------------------------------------
__global__ void k_epi(const float* __restrict__ wt1w, const float* __restrict__ wt1b,
                      const float* __restrict__ wt2w, const float* __restrict__ wt2b,
                      float* __restrict__ out) {
    __shared__ float cs[KK * Hh], hp[KK * Hh], w1s[Hh], w2s[Hh];
    int tid = threadIdx.x;  // 128
    for (int i = tid; i < KK * Hh; i += 128) { cs[i] = g_centers[i]; hp[i] = g_hprime[i]; }
    for (int i = tid; i < Hh; i += 128)      { w1s[i] = wt1w[i]; w2s[i] = wt2w[i]; }
    __syncthreads();

    int warp = tid >> 5, lane = tid & 31;
    int b = blockIdx.x * 4 + warp;

    float e[KK];
#pragma unroll
    for (int k = 0; k < KK; k++) e[k] = 0.0f;
    float hv[8];
#pragma unroll
    for (int i = 0; i < 8; i++) {
        int d = lane + i * 32;
        float v = g_hA[(size_t)b * Hh + d];
        hv[i] = v;
#pragma unroll
        for (int k = 0; k < KK; k++) e[k] += v * cs[k * Hh + d];
    }
#pragma unroll
    for (int k = 0; k < KK; k++)
#pragma unroll
        for (int o = 16; o > 0; o >>= 1)
            e[k] += __shfl_xor_sync(0xffffffffu, e[k], o);

    float mx = 0.0f;
#pragma unroll
    for (int k = 0; k < KK; k++) { e[k] = fmaxf(e[k], 0.0f); mx = fmaxf(mx, e[k]); }
    float den = 0.0f, sc[KK];
#pragma unroll
    for (int k = 0; k < KK; k++) { sc[k] = expf(e[k] - mx); den += sc[k]; }
    float inv = 1.0f / den;
#pragma unroll
    for (int k = 0; k < KK; k++) sc[k] *= inv;

    float w1p = 0.0f, w2p = 0.0f, cl[8];
#pragma unroll
    for (int i = 0; i < 8; i++) {
        int d = lane + i * 32;
        float s = 0.0f;
#pragma unroll
        for (int k = 0; k < KK; k++) s += sc[k] * hp[k * Hh + d];
        cl[i] = s;
        w1p += s * w1s[d];
        w2p += hv[i] * w2s[d];
    }
#pragma unroll
    for (int o = 16; o > 0; o >>= 1) {
        w1p += __shfl_xor_sync(0xffffffffu, w1p, o);
        w2p += __shfl_xor_sync(0xffffffffu, w2p, o);
    }
    float w1 = 1.0f / (1.0f + expf(-(w1p + wt1b[0])));
    float w2 = 1.0f / (1.0f + expf(-(w2p + wt2b[0])));
    float w1n = w1 / (w1 + w2 + 1e-8f);
#pragma unroll
    for (int i = 0; i < 8; i++) {
        int d = lane + i * 32;
        out[(size_t)b * Hh + d] = w1n * cl[i] + (1.0f - w1n) * hv[i];
    }
}

// ---------------- host: JAX threefry replication -----------------------------
static inline uint32_t rotl32(uint32_t v, int d) { return (v << d) | (v >> (32 - d)); }

static void threefry2x32(uint32_t k0, uint32_t k1, uint32_t c0, uint32_t c1,
                         uint32_t* o0, uint32_t* o1) {
    uint32_t ks0 = k0, ks1 = k1, ks2 = k0 ^ k1 ^ 0x1BD11BDAu;
    uint32_t x0 = c0 + ks0, x1 = c1 + ks1;
    const int rA[4] = {13, 15, 26, 6};
    const int rB[4] = {17, 29, 16, 24};
#define TF4(R) for (int i_ = 0; i_ < 4; i_++) { x0 += x1; x1 = rotl32(x1, R[i_]); x1 ^= x0; }
    TF4(rA); x0 += ks1; x1 += ks2 + 1u;
    TF4(rB); x0 += ks2; x1 += ks0 + 2u;
    TF4(rA); x0 += ks0; x1 += ks1 + 3u;
    TF4(rB); x0 += ks1; x1 += ks2 + 4u;
    TF4(rA); x0 += ks2; x1 += ks0 + 5u;
#undef TF4
    *o0 = x0; *o1 = x1;
}

static void compute_init_indices(int* out12) {
    uint32_t sk0, sk1;
    threefry2x32(0u, 42u, 0u, 1u, &sk0, &sk1);
    uint32_t keys[Bsz];
    for (int i = 0; i < Bsz; i++) {
        uint32_t o0, o1;
        threefry2x32(sk0, sk1, 0u, (uint32_t)i, &o0, &o1);
        keys[i] = o0 ^ o1;
    }
    int idx[Bsz];
    for (int i = 0; i < Bsz; i++) idx[i] = i;
    std::stable_sort(idx, idx + Bsz,
                     [&](int a, int b) { return keys[a] < keys[b]; });
    for (int k = 0; k < KK; k++) out12[k] = idx[k];
}

// ---------------- launch -----------------------------------------------------
extern "C" void kernel_launch(void* const* d_in, const int* in_sizes, int n_in,
                              void* d_out, int out_size) {
    const float* x       = (const float*)d_in[0];
    const int*   lengths = (const int*)  d_in[1];
    const float* w_ih    = (const float*)d_in[2];
    const float* w_hh    = (const float*)d_in[3];
    const float* b_ih    = (const float*)d_in[4];
    const float* b_hh    = (const float*)d_in[5];
    const float* g1w     = (const float*)d_in[6];
    const float* g1b     = (const float*)d_in[7];
    const float* g2w     = (const float*)d_in[8];
    const float* g2b     = (const float*)d_in[9];
    const float* wt1w    = (const float*)d_in[10];
    const float* wt1b    = (const float*)d_in[11];
    const float* wt2w    = (const float*)d_in[12];
    const float* wt2b    = (const float*)d_in[13];
    float* out = (float*)d_out;
    (void)in_sizes; (void)n_in; (void)out_size;

    IdxList il;
    compute_init_indices(il.v);

    k_init<<<1024, 256>>>();
    k_alive<<<(Tt * Bsz + 255) / 256, 256>>>(lengths);
    k_trans<<<(G3H * Hh + 255) / 256, 256>>>(w_hh);
    k_sort<<<1, 1024>>>(lengths);
    k_xproj<<<dim3(12, 1600), 256>>>(x, w_ih, b_ih);
    k_scan<<<NSCAN, 256>>>(b_hh, lengths);
    k_cinit<<<1, 256>>>(il);
    for (int it = 0; it < KMI; it++) {
        k_assign<<<256, 128>>>();
        k_update<<<KK, 256>>>();
    }
    k_hprime<<<KK, 256>>>(g1w, g1b, g2w, g2b);
    k_epi<<<256, 128>>>(wt1w, wt1b, wt2w, wt2b, out);
}